// round 9
// baseline (speedup 1.0000x reference)
#include <cuda_runtime.h>
#include <math.h>

#define L_TOTAL 131072
#define NBATCH  8
#define CHUNK   16
#define FWARM   128
#define ENVW    256
#define SKEW    8
#define NCHUNK  (L_TOTAL / CHUNK)            // 8192
#define NPAIR   (NCHUNK / 2)                 // 4096
#define NTHREADS (NPAIR * NBATCH)            // 32768
#define BLOCK   256                          // 8 warps -> 2 per SMSP
#define ITERS   (CHUNK + FWARM + SKEW)       // 152
#define WSTART  (FWARM + SKEW)               // 136

__device__ __forceinline__ float ex2a(float x) {
    float y; asm("ex2.approx.ftz.f32 %0, %1;" : "=f"(y) : "f"(x)); return y;
}
__device__ __forceinline__ float rcpa(float x) {
    float y; asm("rcp.approx.ftz.f32 %0, %1;" : "=f"(y) : "f"(x)); return y;
}

struct Coef { float b0, b1, b2, a1, a2; };

__device__ __forceinline__ float bqstep(const Coef& c, float x, float& s1, float& s2) {
    float y = fmaf(c.b0, x, s1);
    float t = fmaf(c.b1, x, s2);
    s1 = fmaf(-c.a1, y, t);
    s2 = fmaf(-c.a2, y, c.b2 * x);
    return y;
}

__device__ __forceinline__ Coef mk_stable(float r0, float r1, float r2, float r3, float r4) {
    float a1 = 2.f * tanhf(r3);
    float aa = fabsf(a1);
    float a2 = 0.5f * fmaf(2.f - aa, tanhf(r4), aa);
    Coef c; c.b0 = r0; c.b1 = r1; c.b2 = r2; c.a1 = a1; c.a2 = a2;
    return c;
}

struct GruC {
    float rwx, rwh, rc, zwx, zwh, zc, wi2n, bi2n, wh2n, bh2n, ow, ob;
};

template<bool GUARDED>
__device__ __forceinline__ float pipe_step(
    float xv, int it, int gg,
    const Coef& c1, const Coef& c2, const Coef& c3, const Coef& c4, const Coef& cf,
    const GruC& G, float cenv, float ccenv, float depth, float fbmix,
    float& env, float& h,
    float& d0, float& d1, float& d2, float& d3,
    float& d4, float& d5, float& d6, float& d7,
    float& s11, float& s12, float& s21, float& s22,
    float& s31, float& s32, float& s41, float& s42,
    float& sf1, float& sf2)
{
    float y1 = bqstep(c1, d0, s11, s12);
    float y2 = bqstep(c2, d1, s21, s22);

    float er = ex2a(fmaf(h, G.rwh, fmaf(d2, G.rwx, G.rc)));
    float ez = ex2a(fmaf(h, G.zwh, fmaf(d2, G.zwx, G.zc)));
    float r = rcpa(1.f + er);
    float z = rcpa(1.f + ez);
    float gi2s = fmaf(d2, G.wi2n, G.bi2n);
    float gh2s = fmaf(h, G.wh2n, G.bh2n);
    float en = ex2a(fmaf(r, gh2s, gi2s));
    float n = fmaf(2.f, rcpa(1.f + en), -1.f);
    float hn = fmaf(z, h - n, n);
    if (GUARDED) h = (it >= gg) ? hn : 0.f;   // predicated select, no branch
    else         h = hn;
    float y3 = fmaf(h, G.ow, G.ob);

    float y4 = bqstep(c3, d3, s31, s32);
    float y5 = bqstep(c4, d4, s41, s42);
    float yfb = bqstep(cf, d7, sf1, sf2);
    float ov = fmaf(-fbmix, yfb, d7);

    env = fmaf(cenv, env, ccenv * fabsf(xv));
    float y0 = xv * fmaf(-depth, env, 1.f);

    d7 = d6; d6 = d5; d5 = y5; d4 = y4; d3 = y3; d2 = y2; d1 = y1; d0 = y0;
    return ov;
}

__global__ void __launch_bounds__(BLOCK, 1) amp_kernel(
    const float* __restrict__ X,     const float* __restrict__ knobs,
    const float* __restrict__ ecr,   const float* __restrict__ prep,
    const float* __restrict__ postp, const float* __restrict__ gwi,
    const float* __restrict__ gwh,   const float* __restrict__ gbi,
    const float* __restrict__ gbh,   const float* __restrict__ gow,
    const float* __restrict__ gob,   const float* __restrict__ sw1,
    const float* __restrict__ sb1,   const float* __restrict__ sw2,
    const float* __restrict__ sb2,   const float* __restrict__ fw1,
    const float* __restrict__ fb1,   const float* __restrict__ fw2,
    const float* __restrict__ fb2,   const float* __restrict__ famt,
    float* __restrict__ OUT)
{
    const int tid = blockIdx.x * BLOCK + threadIdx.x;
    if (tid >= NTHREADS) return;
    // lane-adjacent chunk mapping: whole warp works on ONE batch row,
    // adjacent lanes on adjacent chunks -> 16-line (not 32-line) vector accesses
    const int b  = tid >> 12;                 // tid / NPAIR
    const int cp = tid & (NPAIR - 1);

    // ---------------- per-batch setup ----------------
    const float cenv  = 1.f / (1.f + expf(-ecr[0]));
    const float ccenv = 1.f - cenv;

    const float k0 = knobs[b * 3 + 0];
    float acc = sb2[0];
#pragma unroll
    for (int j = 0; j < 8; j++) acc += sw2[j] * tanhf(fmaf(k0, sw1[j], sb1[j]));
    const float depth = 1.f / (1.f + expf(-acc));

    const Coef c1 = mk_stable(prep[0], prep[1], prep[2], prep[3], prep[4]);
    const Coef c2 = mk_stable(prep[5], prep[6], prep[7], prep[8], prep[9]);
    const Coef c3 = mk_stable(postp[0], postp[1], postp[2], postp[3], postp[4]);
    const Coef c4 = mk_stable(postp[5], postp[6], postp[7], postp[8], postp[9]);

    Coef cf;
    {
        const float k1 = knobs[b * 3 + 1], k2 = knobs[b * 3 + 2];
        float h16[16];
#pragma unroll
        for (int j = 0; j < 16; j++)
            h16[j] = tanhf(fmaf(k1, fw1[j * 2 + 0], fmaf(k2, fw1[j * 2 + 1], fb1[j])));
        float raw[5];
#pragma unroll
        for (int i = 0; i < 5; i++) {
            float a = fb2[i];
#pragma unroll
            for (int j = 0; j < 16; j++) a = fmaf(fw2[i * 16 + j], h16[j], a);
            raw[i] = a;
        }
        cf = mk_stable(raw[0], raw[1], raw[2], raw[3], raw[4]);
    }
    const float fbmix = 1.f / (1.f + expf(-famt[0]));

    const float L2E = 1.4426950408889634f;
    const float NL2E = -2.f * L2E;
    GruC G;
    G.rwx = -L2E * gwi[0]; G.rwh = -L2E * gwh[0]; G.rc = -L2E * (gbi[0] + gbh[0]);
    G.zwx = -L2E * gwi[1]; G.zwh = -L2E * gwh[1]; G.zc = -L2E * (gbi[1] + gbh[1]);
    G.wi2n = NL2E * gwi[2]; G.bi2n = NL2E * gbi[2];
    G.wh2n = NL2E * gwh[2]; G.bh2n = NL2E * gbh[2];
    G.ow = gow[0]; G.ob = gob[0];

    const float* __restrict__ xr = X + (size_t)b * L_TOTAL;
    float* __restrict__ orow     = OUT + (size_t)b * L_TOTAL;

    // ---------------- stream state ----------------
    int   fb_[2], gg_[2];
    float env[2], hh[2];
    float d0[2], d1[2], d2[2], d3[2], d4[2], d5[2], d6[2], d7[2];
    float s11[2], s12[2], s21[2], s22[2], s31[2], s32[2], s41[2], s42[2], sf1[2], sf2[2];

#pragma unroll
    for (int k = 0; k < 2; k++) {
        const int c = cp + k * NPAIR;
        fb_[k] = c * CHUNK - FWARM;                 // 16-aligned, may be negative
        int g = 3 - fb_[k]; if (g < 3) g = 3;
        gg_[k] = g;
        env[k] = 0.f; hh[k] = 0.f;
        d0[k]=d1[k]=d2[k]=d3[k]=d4[k]=d5[k]=d6[k]=d7[k]=0.f;
        s11[k]=s12[k]=s21[k]=s22[k]=s31[k]=s32[k]=s41[k]=s42[k]=sf1[k]=sf2[k]=0.f;
    }

    // ---------------- exact envelope pre-scan (zero-history exact) ----------------
    {
        const float cc2 = cenv * cenv, cc4 = cc2 * cc2;
        const float g0 = ccenv * cenv * cc2;
        const float g1 = ccenv * cc2;
        const float g2 = ccenv * cenv;
        const float g3 = ccenv;
#pragma unroll
        for (int k = 0; k < 2; k++) {
            int t0 = fb_[k] - ENVW; if (t0 < 0) t0 = 0;
            float e = 0.f;
            for (int t = t0; t < fb_[k]; t += 4) {
                float4 v = *reinterpret_cast<const float4*>(xr + t);
                float a = g0 * fabsf(v.x);
                a = fmaf(g1, fabsf(v.y), a);
                a = fmaf(g2, fabsf(v.z), a);
                a = fmaf(g3, fabsf(v.w), a);
                e = fmaf(cc4, e, a);
            }
            env[k] = e;
        }
    }

#define PSTEP(G_, k_, xv_, it_) pipe_step<G_>(xv_, it_, gg_[k_], c1, c2, c3, c4, cf, G, \
        cenv, ccenv, depth, fbmix, env[k_], hh[k_], d0[k_], d1[k_], d2[k_], d3[k_],     \
        d4[k_], d5[k_], d6[k_], d7[k_], s11[k_], s12[k_], s21[k_], s22[k_],             \
        s31[k_], s32[k_], s41[k_], s42[k_], sf1[k_], sf2[k_])

    // ---------------- prologue (SKEW scalar iters, select-guarded) ----------------
#pragma unroll
    for (int i = 0; i < SKEW; i++) {
#pragma unroll
        for (int k = 0; k < 2; k++) {
            int s = fb_[k] + i;
            int sa = s < 0 ? 0 : s;
            float xv = xr[sa];
            xv = (s >= 0) ? xv : 0.f;
            (void)PSTEP(true, k, xv, i);
        }
    }

    // ---------------- warm loop (no stores, masked loads, guarded GRU) ----------------
    for (int i = SKEW; i < WSTART; i += 4) {
        float xv4[2][4];
#pragma unroll
        for (int k = 0; k < 2; k++) {
            int s = fb_[k] + i;
            int sa = s < 0 ? 0 : s;            // groups 4-aligned: all-in or all-out
            float4 v = *reinterpret_cast<const float4*>(xr + sa);
            float m = (s >= 0) ? 1.f : 0.f;
            xv4[k][0] = v.x * m; xv4[k][1] = v.y * m;
            xv4[k][2] = v.z * m; xv4[k][3] = v.w * m;
        }
#pragma unroll
        for (int j = 0; j < 4; j++)
#pragma unroll
            for (int k = 0; k < 2; k++)
                (void)PSTEP(true, k, xv4[k][j], i + j);
    }

    // ---------------- output loop (unconditional stores, clean body) ----------------
    for (int i = WSTART; i < ITERS; i += 4) {
        float xv4[2][4];
#pragma unroll
        for (int k = 0; k < 2; k++) {
            int s = fb_[k] + i;
            int sa = s > (L_TOTAL - 4) ? (L_TOTAL - 4) : s;  // tail over-read is dead data
            float4 v = *reinterpret_cast<const float4*>(xr + sa);
            xv4[k][0] = v.x; xv4[k][1] = v.y; xv4[k][2] = v.z; xv4[k][3] = v.w;
        }
        float ov4[2][4];
#pragma unroll
        for (int j = 0; j < 4; j++)
#pragma unroll
            for (int k = 0; k < 2; k++)
                ov4[k][j] = PSTEP(false, k, xv4[k][j], i + j);
#pragma unroll
        for (int k = 0; k < 2; k++) {
            int s = fb_[k] + i;
            float4 o; o.x=ov4[k][0]; o.y=ov4[k][1]; o.z=ov4[k][2]; o.w=ov4[k][3];
            *reinterpret_cast<float4*>(orow + (s - SKEW)) = o;
        }
    }
#undef PSTEP
}

extern "C" void kernel_launch(void* const* d_in, const int* in_sizes, int n_in,
                              void* d_out, int out_size)
{
    const float* X     = (const float*)d_in[0];
    const float* knobs = (const float*)d_in[1];
    const float* ecr   = (const float*)d_in[2];
    const float* prep  = (const float*)d_in[3];
    const float* postp = (const float*)d_in[4];
    const float* gwi   = (const float*)d_in[5];
    const float* gwh   = (const float*)d_in[6];
    const float* gbi   = (const float*)d_in[7];
    const float* gbh   = (const float*)d_in[8];
    const float* gow   = (const float*)d_in[9];
    const float* gob   = (const float*)d_in[10];
    const float* sw1   = (const float*)d_in[11];
    const float* sb1   = (const float*)d_in[12];
    const float* sw2   = (const float*)d_in[13];
    const float* sb2   = (const float*)d_in[14];
    const float* fw1   = (const float*)d_in[15];
    const float* fb1   = (const float*)d_in[16];
    const float* fw2   = (const float*)d_in[17];
    const float* fb2   = (const float*)d_in[18];
    const float* famt  = (const float*)d_in[19];
    float* OUT = (float*)d_out;

    dim3 grid(NTHREADS / BLOCK);   // 128 blocks x 256 threads: 2 warps/SMSP, 2 streams/thread
    amp_kernel<<<grid, BLOCK>>>(X, knobs, ecr, prep, postp, gwi, gwh, gbi, gbh,
                                gow, gob, sw1, sb1, sw2, sb2, fw1, fb1, fw2, fb2,
                                famt, OUT);
}

// round 10
// speedup vs baseline: 1.1192x; 1.1192x over previous
#include <cuda_runtime.h>
#include <math.h>

#define L_TOTAL 131072
#define NBATCH  8
#define CHUNK   16
#define FWARM   96
#define ENVW    256
#define SKEW    8
#define NCHUNK  (L_TOTAL / CHUNK)            // 8192
#define NTHREADS (NCHUNK * NBATCH)           // 65536
#define BLOCK   512                          // 16 warps/SM -> 4 per SMSP
#define ITERS   (CHUNK + FWARM + SKEW)       // 120
#define WSTART  (FWARM + SKEW)               // 104

__device__ __forceinline__ float ex2a(float x) {
    float y; asm("ex2.approx.ftz.f32 %0, %1;" : "=f"(y) : "f"(x)); return y;
}
__device__ __forceinline__ float rcpa(float x) {
    float y; asm("rcp.approx.ftz.f32 %0, %1;" : "=f"(y) : "f"(x)); return y;
}

struct Coef { float b0, b1, b2, a1, a2; };

__device__ __forceinline__ float bqstep(const Coef& c, float x, float& s1, float& s2) {
    float y = fmaf(c.b0, x, s1);
    float t = fmaf(c.b1, x, s2);
    s1 = fmaf(-c.a1, y, t);
    s2 = fmaf(-c.a2, y, c.b2 * x);
    return y;
}

__device__ __forceinline__ Coef mk_stable(float r0, float r1, float r2, float r3, float r4) {
    float a1 = 2.f * tanhf(r3);
    float aa = fabsf(a1);
    float a2 = 0.5f * fmaf(2.f - aa, tanhf(r4), aa);
    Coef c; c.b0 = r0; c.b1 = r1; c.b2 = r2; c.a1 = a1; c.a2 = a2;
    return c;
}

struct GruC {
    float rwx, rwh, rc, zwx, zwh, zc, wi2n, bi2n, wh2n, bh2n, ow, ob;
};

// One pipeline step. GUARDED enables the GRU-start predicated select.
template<bool GUARDED>
__device__ __forceinline__ float pipe_step(
    float xv, int it, int gg,
    const Coef& c1, const Coef& c2, const Coef& c3, const Coef& c4, const Coef& cf,
    const GruC& G, float cenv, float ccenv, float depth, float fbmix,
    float& env, float& h,
    float& d0, float& d1, float& d2, float& d3,
    float& d4, float& d5, float& d6, float& d7,
    float& s11, float& s12, float& s21, float& s22,
    float& s31, float& s32, float& s41, float& s42,
    float& sf1, float& sf2)
{
    float y1 = bqstep(c1, d0, s11, s12);
    float y2 = bqstep(c2, d1, s21, s22);

    // GRU (chain ~92 cyc): FFMA->EX2->FADD->RCP->FFMA->EX2->FADD->RCP->FFMA->FADD->FFMA
    float er = ex2a(fmaf(h, G.rwh, fmaf(d2, G.rwx, G.rc)));
    float ez = ex2a(fmaf(h, G.zwh, fmaf(d2, G.zwx, G.zc)));
    float r = rcpa(1.f + er);
    float z = rcpa(1.f + ez);
    float gi2s = fmaf(d2, G.wi2n, G.bi2n);
    float gh2s = fmaf(h, G.wh2n, G.bh2n);
    float en = ex2a(fmaf(r, gh2s, gi2s));
    float n = fmaf(2.f, rcpa(1.f + en), -1.f);
    float hn = fmaf(z, h - n, n);
    if (GUARDED) h = (it >= gg) ? hn : 0.f;   // predicated select, no branch
    else         h = hn;
    float y3 = fmaf(h, G.ow, G.ob);

    float y4 = bqstep(c3, d3, s31, s32);
    float y5 = bqstep(c4, d4, s41, s42);
    float yfb = bqstep(cf, d7, sf1, sf2);
    float ov = fmaf(-fbmix, yfb, d7);

    env = fmaf(cenv, env, ccenv * fabsf(xv));
    float y0 = xv * fmaf(-depth, env, 1.f);

    d7 = d6; d6 = d5; d5 = y5; d4 = y4; d3 = y3; d2 = y2; d1 = y1; d0 = y0;
    return ov;
}

__global__ void __launch_bounds__(BLOCK, 1) amp_kernel(
    const float* __restrict__ X,     const float* __restrict__ knobs,
    const float* __restrict__ ecr,   const float* __restrict__ prep,
    const float* __restrict__ postp, const float* __restrict__ gwi,
    const float* __restrict__ gwh,   const float* __restrict__ gbi,
    const float* __restrict__ gbh,   const float* __restrict__ gow,
    const float* __restrict__ gob,   const float* __restrict__ sw1,
    const float* __restrict__ sb1,   const float* __restrict__ sw2,
    const float* __restrict__ sb2,   const float* __restrict__ fw1,
    const float* __restrict__ fb1,   const float* __restrict__ fw2,
    const float* __restrict__ fb2,   const float* __restrict__ famt,
    float* __restrict__ OUT)
{
    const int tid = blockIdx.x * BLOCK + threadIdx.x;
    if (tid >= NTHREADS) return;
    // whole warp on ONE batch row, adjacent lanes on adjacent chunks
    const int b  = tid >> 13;                 // tid / NCHUNK
    const int cp = tid & (NCHUNK - 1);

    // ---------------- per-batch setup ----------------
    const float cenv  = 1.f / (1.f + expf(-ecr[0]));
    const float ccenv = 1.f - cenv;

    const float k0 = knobs[b * 3 + 0];
    float acc = sb2[0];
#pragma unroll
    for (int j = 0; j < 8; j++) acc += sw2[j] * tanhf(fmaf(k0, sw1[j], sb1[j]));
    const float depth = 1.f / (1.f + expf(-acc));

    const Coef c1 = mk_stable(prep[0], prep[1], prep[2], prep[3], prep[4]);
    const Coef c2 = mk_stable(prep[5], prep[6], prep[7], prep[8], prep[9]);
    const Coef c3 = mk_stable(postp[0], postp[1], postp[2], postp[3], postp[4]);
    const Coef c4 = mk_stable(postp[5], postp[6], postp[7], postp[8], postp[9]);

    Coef cf;
    {
        const float k1 = knobs[b * 3 + 1], k2 = knobs[b * 3 + 2];
        float h16[16];
#pragma unroll
        for (int j = 0; j < 16; j++)
            h16[j] = tanhf(fmaf(k1, fw1[j * 2 + 0], fmaf(k2, fw1[j * 2 + 1], fb1[j])));
        float raw[5];
#pragma unroll
        for (int i = 0; i < 5; i++) {
            float a = fb2[i];
#pragma unroll
            for (int j = 0; j < 16; j++) a = fmaf(fw2[i * 16 + j], h16[j], a);
            raw[i] = a;
        }
        cf = mk_stable(raw[0], raw[1], raw[2], raw[3], raw[4]);
    }
    const float fbmix = 1.f / (1.f + expf(-famt[0]));

    const float L2E = 1.4426950408889634f;
    const float NL2E = -2.f * L2E;
    GruC G;
    G.rwx = -L2E * gwi[0]; G.rwh = -L2E * gwh[0]; G.rc = -L2E * (gbi[0] + gbh[0]);
    G.zwx = -L2E * gwi[1]; G.zwh = -L2E * gwh[1]; G.zc = -L2E * (gbi[1] + gbh[1]);
    G.wi2n = NL2E * gwi[2]; G.bi2n = NL2E * gbi[2];
    G.wh2n = NL2E * gwh[2]; G.bh2n = NL2E * gbh[2];
    G.ow = gow[0]; G.ob = gob[0];

    const float* __restrict__ xr = X + (size_t)b * L_TOTAL;
    float* __restrict__ orow     = OUT + (size_t)b * L_TOTAL;

    // ---------------- stream state ----------------
    const int fb = cp * CHUNK - FWARM;            // 16-aligned, may be negative
    int gg = 3 - fb; if (gg < 3) gg = 3;          // GRU start iteration

    float env = 0.f, h = 0.f;
    float d0 = 0.f, d1 = 0.f, d2 = 0.f, d3 = 0.f;
    float d4 = 0.f, d5 = 0.f, d6 = 0.f, d7 = 0.f;
    float s11 = 0.f, s12 = 0.f, s21 = 0.f, s22 = 0.f;
    float s31 = 0.f, s32 = 0.f, s41 = 0.f, s42 = 0.f, sf1 = 0.f, sf2 = 0.f;

    // ---------------- exact envelope pre-scan (zero-history exact) ----------------
    {
        const float cc2 = cenv * cenv, cc4 = cc2 * cc2;
        const float g0 = ccenv * cenv * cc2;
        const float g1 = ccenv * cc2;
        const float g2 = ccenv * cenv;
        const float g3 = ccenv;
        int t0 = fb - ENVW; if (t0 < 0) t0 = 0;
        float e = 0.f;
        for (int t = t0; t < fb; t += 4) {
            float4 v = *reinterpret_cast<const float4*>(xr + t);
            float a = g0 * fabsf(v.x);
            a = fmaf(g1, fabsf(v.y), a);
            a = fmaf(g2, fabsf(v.z), a);
            a = fmaf(g3, fabsf(v.w), a);
            e = fmaf(cc4, e, a);
        }
        env = e;
    }

#define PSTEP(G_, xv_, it_) pipe_step<G_>(xv_, it_, gg, c1, c2, c3, c4, cf, G, \
        cenv, ccenv, depth, fbmix, env, h, d0, d1, d2, d3, d4, d5, d6, d7,     \
        s11, s12, s21, s22, s31, s32, s41, s42, sf1, sf2)

    // ---------------- prologue (SKEW scalar iters, select-guarded) ----------------
#pragma unroll
    for (int i = 0; i < SKEW; i++) {
        int s = fb + i;
        int sa = s < 0 ? 0 : s;
        float xv = xr[sa];
        xv = (s >= 0) ? xv : 0.f;
        (void)PSTEP(true, xv, i);
    }

    // ---------------- warm loop (no stores, masked loads, guarded GRU) ----------------
    for (int i = SKEW; i < WSTART; i += 4) {
        int s = fb + i;
        int sa = s < 0 ? 0 : s;                   // 4-aligned groups: all-in or all-out
        float4 v = *reinterpret_cast<const float4*>(xr + sa);
        float m = (s >= 0) ? 1.f : 0.f;
        float xv4[4] = { v.x * m, v.y * m, v.z * m, v.w * m };
#pragma unroll
        for (int j = 0; j < 4; j++)
            (void)PSTEP(true, xv4[j], i + j);
    }

    // ---------------- output loop (unconditional stores, clean body) ----------------
    for (int i = WSTART; i < ITERS; i += 4) {
        int s = fb + i;
        int sa = s > (L_TOTAL - 4) ? (L_TOTAL - 4) : s;  // tail over-read is dead data
        float4 v = *reinterpret_cast<const float4*>(xr + sa);
        float xv4[4] = { v.x, v.y, v.z, v.w };
        float ov4[4];
#pragma unroll
        for (int j = 0; j < 4; j++)
            ov4[j] = PSTEP(false, xv4[j], i + j);
        float4 o; o.x = ov4[0]; o.y = ov4[1]; o.z = ov4[2]; o.w = ov4[3];
        *reinterpret_cast<float4*>(orow + (s - SKEW)) = o;
    }
#undef PSTEP
}

extern "C" void kernel_launch(void* const* d_in, const int* in_sizes, int n_in,
                              void* d_out, int out_size)
{
    const float* X     = (const float*)d_in[0];
    const float* knobs = (const float*)d_in[1];
    const float* ecr   = (const float*)d_in[2];
    const float* prep  = (const float*)d_in[3];
    const float* postp = (const float*)d_in[4];
    const float* gwi   = (const float*)d_in[5];
    const float* gwh   = (const float*)d_in[6];
    const float* gbi   = (const float*)d_in[7];
    const float* gbh   = (const float*)d_in[8];
    const float* gow   = (const float*)d_in[9];
    const float* gob   = (const float*)d_in[10];
    const float* sw1   = (const float*)d_in[11];
    const float* sb1   = (const float*)d_in[12];
    const float* sw2   = (const float*)d_in[13];
    const float* sb2   = (const float*)d_in[14];
    const float* fw1   = (const float*)d_in[15];
    const float* fb1   = (const float*)d_in[16];
    const float* fw2   = (const float*)d_in[17];
    const float* fb2   = (const float*)d_in[18];
    const float* famt  = (const float*)d_in[19];
    float* OUT = (float*)d_out;

    dim3 grid(NTHREADS / BLOCK);   // 128 blocks x 512 threads: 4 independent warps per SMSP
    amp_kernel<<<grid, BLOCK>>>(X, knobs, ecr, prep, postp, gwi, gwh, gbi, gbh,
                                gow, gob, sw1, sb1, sw2, sb2, fw1, fb1, fw2, fb2,
                                famt, OUT);
}

// round 11
// speedup vs baseline: 1.1737x; 1.0487x over previous
#include <cuda_runtime.h>
#include <math.h>

#define L_TOTAL 131072
#define NBATCH  8
#define CHUNK   16
#define FWARM   80
#define ENVW    256
#define SKEW    8
#define NCHUNK  (L_TOTAL / CHUNK)            // 8192
#define NTHREADS (NCHUNK * NBATCH)           // 65536
#define BLOCK   512                          // 4 warps per SMSP
#define ITERS   (CHUNK + FWARM + SKEW)       // 104
#define WSTART  (FWARM + SKEW)               // 88

typedef unsigned long long u64;

__device__ __forceinline__ float ex2a(float x) {
    float y; asm("ex2.approx.ftz.f32 %0, %1;" : "=f"(y) : "f"(x)); return y;
}
__device__ __forceinline__ float rcpa(float x) {
    float y; asm("rcp.approx.ftz.f32 %0, %1;" : "=f"(y) : "f"(x)); return y;
}
__device__ __forceinline__ u64 pk2(float lo, float hi) {
    u64 r; asm("mov.b64 %0, {%1, %2};" : "=l"(r) : "f"(lo), "f"(hi)); return r;
}
__device__ __forceinline__ void upk2(u64 v, float& lo, float& hi) {
    asm("mov.b64 {%0, %1}, %2;" : "=f"(lo), "=f"(hi) : "l"(v));
}
// packed fp32 pair FMA/MUL: identical IEEE-rn semantics per lane, 2 flops per fma-pipe slot
__device__ __forceinline__ u64 fma2(u64 a, u64 b, u64 c) {
    u64 r; asm("fma.rn.f32x2 %0, %1, %2, %3;" : "=l"(r) : "l"(a), "l"(b), "l"(c)); return r;
}
__device__ __forceinline__ u64 mul2(u64 a, u64 b) {
    u64 r; asm("mul.rn.f32x2 %0, %1, %2;" : "=l"(r) : "l"(a), "l"(b)); return r;
}

__device__ __forceinline__ void mk_stable5(const float* p, float* out) {
    float a1 = 2.f * tanhf(p[3]);
    float aa = fabsf(a1);
    float a2 = 0.5f * fmaf(2.f - aa, tanhf(p[4]), aa);
    out[0] = p[0]; out[1] = p[1]; out[2] = p[2]; out[3] = a1; out[4] = a2;
}

__global__ void __launch_bounds__(BLOCK, 1) amp_kernel(
    const float* __restrict__ X,     const float* __restrict__ knobs,
    const float* __restrict__ ecr,   const float* __restrict__ prep,
    const float* __restrict__ postp, const float* __restrict__ gwi,
    const float* __restrict__ gwh,   const float* __restrict__ gbi,
    const float* __restrict__ gbh,   const float* __restrict__ gow,
    const float* __restrict__ gob,   const float* __restrict__ sw1,
    const float* __restrict__ sb1,   const float* __restrict__ sw2,
    const float* __restrict__ sb2,   const float* __restrict__ fw1,
    const float* __restrict__ fb1,   const float* __restrict__ fw2,
    const float* __restrict__ fb2,   const float* __restrict__ famt,
    float* __restrict__ OUT)
{
    const int tid = blockIdx.x * BLOCK + threadIdx.x;
    if (tid >= NTHREADS) return;
    const int b  = tid >> 13;                 // tid / NCHUNK  (warp-uniform)
    const int cp = tid & (NCHUNK - 1);        // adjacent lanes -> adjacent chunks

    // ---------------- per-batch setup ----------------
    const float cenv  = 1.f / (1.f + expf(-ecr[0]));
    const float ccenv = 1.f - cenv;

    const float k0 = knobs[b * 3 + 0];
    float acc = sb2[0];
#pragma unroll
    for (int j = 0; j < 8; j++) acc += sw2[j] * tanhf(fmaf(k0, sw1[j], sb1[j]));
    const float depth = 1.f / (1.f + expf(-acc));

    float cA[5], cB[5], cC[5], cD[5], cF[5];
    mk_stable5(prep + 0, cA);  mk_stable5(prep + 5, cB);
    mk_stable5(postp + 0, cC); mk_stable5(postp + 5, cD);
    {
        const float k1 = knobs[b * 3 + 1], k2 = knobs[b * 3 + 2];
        float h16[16];
#pragma unroll
        for (int j = 0; j < 16; j++)
            h16[j] = tanhf(fmaf(k1, fw1[j * 2 + 0], fmaf(k2, fw1[j * 2 + 1], fb1[j])));
        float raw[5];
#pragma unroll
        for (int i = 0; i < 5; i++) {
            float a = fb2[i];
#pragma unroll
            for (int j = 0; j < 16; j++) a = fmaf(fw2[i * 16 + j], h16[j], a);
            raw[i] = a;
        }
        mk_stable5(raw, cF);
    }
    const float fbmix = 1.f / (1.f + expf(-famt[0]));

    // packed biquad coefficients: pre pair (bq1,bq2), post pair (bq3,bq4)
    const u64 PB0 = pk2(cA[0], cB[0]), PB1 = pk2(cA[1], cB[1]), PB2 = pk2(cA[2], cB[2]);
    const u64 PA1 = pk2(-cA[3], -cB[3]), PA2 = pk2(-cA[4], -cB[4]);
    const u64 QB0 = pk2(cC[0], cD[0]), QB1 = pk2(cC[1], cD[1]), QB2 = pk2(cC[2], cD[2]);
    const u64 QA1 = pk2(-cC[3], -cD[3]), QA2 = pk2(-cC[4], -cD[4]);
    // feedback biquad: internal packing (b0,b1) and (-a1,-a2)
    const u64 F01 = pk2(cF[0], cF[1]), FA = pk2(-cF[3], -cF[4]);
    const float f_b2 = cF[2];

    // GRU constants (log2e folded); r/z gate FMAs packed
    const float L2E = 1.4426950408889634f;
    const float NL2E = -2.f * L2E;
    const u64 GWX = pk2(-L2E * gwi[0], -L2E * gwi[1]);
    const u64 GWH = pk2(-L2E * gwh[0], -L2E * gwh[1]);
    const u64 GC  = pk2(-L2E * (gbi[0] + gbh[0]), -L2E * (gbi[1] + gbh[1]));
    const float wi2n = NL2E * gwi[2], bi2n = NL2E * gbi[2];
    const float wh2n = NL2E * gwh[2], bh2n = NL2E * gbh[2];
    const float ow = gow[0], ob = gob[0];

    const float* __restrict__ xr = X + (size_t)b * L_TOTAL;
    float* __restrict__ orow     = OUT + (size_t)b * L_TOTAL;

    // ---------------- stream state ----------------
    const int fb = cp * CHUNK - FWARM;            // may be negative (zero-padded)
    int gg = 3 - fb; if (gg < 3) gg = 3;          // GRU start iteration (max 83 < WSTART)

    float env = 0.f, h = 0.f;
    float d0 = 0.f, d1 = 0.f, d2 = 0.f, d3 = 0.f;
    float d4 = 0.f, d5 = 0.f, d6 = 0.f, d7 = 0.f;
    u64 S1p = 0, S2p = 0, S1q = 0, S2q = 0, Sf = 0;   // packed biquad states (zeros)

    // ---------------- exact envelope pre-scan ----------------
    {
        const float cc2 = cenv * cenv, cc4 = cc2 * cc2;
        const float g0 = ccenv * cenv * cc2;
        const float g1 = ccenv * cc2;
        const float g2 = ccenv * cenv;
        const float g3 = ccenv;
        int t0 = fb - ENVW; if (t0 < 0) t0 = 0;
        float e = 0.f;
        for (int t = t0; t < fb; t += 4) {
            float4 v = *reinterpret_cast<const float4*>(xr + t);
            float a = g0 * fabsf(v.x);
            a = fmaf(g1, fabsf(v.y), a);
            a = fmaf(g2, fabsf(v.z), a);
            a = fmaf(g3, fabsf(v.w), a);
            e = fmaf(cc4, e, a);
        }
        env = e;
    }

    // one pipeline step; 'guarded' is always a literal at the call site
    auto step = [&](float xv, int it, bool guarded) -> float {
        // pre pair: bq1 on d0 (lo), bq2 on d1 (hi)
        u64 x01 = pk2(d0, d1);
        u64 Y  = fma2(PB0, x01, S1p);
        u64 T  = fma2(PB1, x01, S2p);
        u64 BX = mul2(PB2, x01);
        S1p = fma2(PA1, Y, T);
        S2p = fma2(PA2, Y, BX);
        float y1, y2; upk2(Y, y1, y2);

        // GRU on d2 (serial chain ~92 cyc)
        u64 az = fma2(GWX, pk2(d2, d2), GC);
        az = fma2(GWH, pk2(h, h), az);
        float ar, azf; upk2(az, ar, azf);
        float er = ex2a(ar), ez = ex2a(azf);
        float r = rcpa(1.f + er);
        float z = rcpa(1.f + ez);
        float gi2s = fmaf(d2, wi2n, bi2n);
        float gh2s = fmaf(h, wh2n, bh2n);
        float en = ex2a(fmaf(r, gh2s, gi2s));
        float n = fmaf(2.f, rcpa(1.f + en), -1.f);
        float hn = fmaf(z, h - n, n);
        h = guarded ? ((it >= gg) ? hn : 0.f) : hn;
        float y3 = fmaf(h, ow, ob);

        // post pair: bq3 on d3 (lo), bq4 on d4 (hi)
        u64 x34 = pk2(d3, d4);
        u64 Yq = fma2(QB0, x34, S1q);
        u64 Tq = fma2(QB1, x34, S2q);
        u64 BXq = mul2(QB2, x34);
        S1q = fma2(QA1, Yq, Tq);
        S2q = fma2(QA2, Yq, BXq);
        float y4, y5; upk2(Yq, y4, y5);

        // feedback biquad on d7 (internal packing)
        u64 Pf = fma2(F01, pk2(d7, d7), Sf);
        float yf, tf; upk2(Pf, yf, tf);
        float b2x = f_b2 * d7;
        Sf = fma2(FA, pk2(yf, yf), pk2(tf, b2x));
        float ov = fmaf(-fbmix, yf, d7);

        // envelope + sag input stage
        env = fmaf(cenv, env, ccenv * fabsf(xv));
        float y0 = xv * fmaf(-depth, env, 1.f);

        d7 = d6; d6 = d5; d5 = y5; d4 = y4; d3 = y3; d2 = y2; d1 = y1; d0 = y0;
        return ov;
    };

    // ---------------- prologue (SKEW scalar iters) ----------------
#pragma unroll
    for (int i = 0; i < SKEW; i++) {
        int s = fb + i;
        int sa = s < 0 ? 0 : s;
        float xv = xr[sa];
        xv = (s >= 0) ? xv : 0.f;
        (void)step(xv, i, true);
    }

    // ---------------- warm loop (no stores, masked loads, guarded GRU) ----------------
    for (int i = SKEW; i < WSTART; i += 4) {
        int s = fb + i;
        int sa = s < 0 ? 0 : s;                   // 4-aligned groups: all-in or all-out
        float4 v = *reinterpret_cast<const float4*>(xr + sa);
        float m = (s >= 0) ? 1.f : 0.f;
        float xv4[4] = { v.x * m, v.y * m, v.z * m, v.w * m };
#pragma unroll
        for (int j = 0; j < 4; j++)
            (void)step(xv4[j], i + j, true);
    }

    // ---------------- output loop (unconditional stores) ----------------
    for (int i = WSTART; i < ITERS; i += 4) {
        int s = fb + i;
        int sa = s > (L_TOTAL - 4) ? (L_TOTAL - 4) : s;  // tail over-read is dead data
        float4 v = *reinterpret_cast<const float4*>(xr + sa);
        float xv4[4] = { v.x, v.y, v.z, v.w };
        float ov4[4];
#pragma unroll
        for (int j = 0; j < 4; j++)
            ov4[j] = step(xv4[j], i + j, false);
        float4 o; o.x = ov4[0]; o.y = ov4[1]; o.z = ov4[2]; o.w = ov4[3];
        *reinterpret_cast<float4*>(orow + (s - SKEW)) = o;
    }
}

extern "C" void kernel_launch(void* const* d_in, const int* in_sizes, int n_in,
                              void* d_out, int out_size)
{
    const float* X     = (const float*)d_in[0];
    const float* knobs = (const float*)d_in[1];
    const float* ecr   = (const float*)d_in[2];
    const float* prep  = (const float*)d_in[3];
    const float* postp = (const float*)d_in[4];
    const float* gwi   = (const float*)d_in[5];
    const float* gwh   = (const float*)d_in[6];
    const float* gbi   = (const float*)d_in[7];
    const float* gbh   = (const float*)d_in[8];
    const float* gow   = (const float*)d_in[9];
    const float* gob   = (const float*)d_in[10];
    const float* sw1   = (const float*)d_in[11];
    const float* sb1   = (const float*)d_in[12];
    const float* sw2   = (const float*)d_in[13];
    const float* sb2   = (const float*)d_in[14];
    const float* fw1   = (const float*)d_in[15];
    const float* fb1   = (const float*)d_in[16];
    const float* fw2   = (const float*)d_in[17];
    const float* fb2   = (const float*)d_in[18];
    const float* famt  = (const float*)d_in[19];
    float* OUT = (float*)d_out;

    dim3 grid(NTHREADS / BLOCK);   // 128 blocks x 512 threads
    amp_kernel<<<grid, BLOCK>>>(X, knobs, ecr, prep, postp, gwi, gwh, gbi, gbh,
                                gow, gob, sw1, sb1, sw2, sb2, fw1, fb1, fw2, fb2,
                                famt, OUT);
}

// round 12
// speedup vs baseline: 1.2799x; 1.0905x over previous
#include <cuda_runtime.h>
#include <math.h>

#define L_TOTAL 131072
#define NBATCH  8
#define CHUNK   16
#define FWARM   64
#define ENVW    256
#define SKEW    8
#define NCHUNK  (L_TOTAL / CHUNK)            // 8192
#define NTHREADS (NCHUNK * NBATCH)           // 65536
#define BLOCK   512                          // 4 warps per SMSP (RF-capped max)
#define ITERS   (CHUNK + FWARM + SKEW)       // 88
#define WSTART  (FWARM + SKEW)               // 72

__device__ __forceinline__ float ex2a(float x) {
    float y; asm("ex2.approx.ftz.f32 %0, %1;" : "=f"(y) : "f"(x)); return y;
}
__device__ __forceinline__ float rcpa(float x) {
    float y; asm("rcp.approx.ftz.f32 %0, %1;" : "=f"(y) : "f"(x)); return y;
}

struct Coef { float b0, b1, b2, a1, a2; };

__device__ __forceinline__ float bqstep(const Coef& c, float x, float& s1, float& s2) {
    float y = fmaf(c.b0, x, s1);
    float t = fmaf(c.b1, x, s2);
    s1 = fmaf(-c.a1, y, t);
    s2 = fmaf(-c.a2, y, c.b2 * x);
    return y;
}

__device__ __forceinline__ Coef mk_stable(float r0, float r1, float r2, float r3, float r4) {
    float a1 = 2.f * tanhf(r3);
    float aa = fabsf(a1);
    float a2 = 0.5f * fmaf(2.f - aa, tanhf(r4), aa);
    Coef c; c.b0 = r0; c.b1 = r1; c.b2 = r2; c.a1 = a1; c.a2 = a2;
    return c;
}

struct GruC {
    float rwx, rwh, rc, zwx, zwh, zc, wi2n, bi2n, wh2n, bh2n, ow, ob;
};

// One pipeline step. GUARDED enables the GRU-start predicated select.
template<bool GUARDED>
__device__ __forceinline__ float pipe_step(
    float xv, int it, int gg,
    const Coef& c1, const Coef& c2, const Coef& c3, const Coef& c4, const Coef& cf,
    const GruC& G, float cenv, float ccenv, float depth, float fbmix,
    float& env, float& h,
    float& d0, float& d1, float& d2, float& d3,
    float& d4, float& d5, float& d6, float& d7,
    float& s11, float& s12, float& s21, float& s22,
    float& s31, float& s32, float& s41, float& s42,
    float& sf1, float& sf2)
{
    float y1 = bqstep(c1, d0, s11, s12);
    float y2 = bqstep(c2, d1, s21, s22);

    // GRU (chain ~92 cyc): FFMA->EX2->FADD->RCP->FFMA->EX2->FADD->RCP->FFMA->FADD->FFMA
    float er = ex2a(fmaf(h, G.rwh, fmaf(d2, G.rwx, G.rc)));
    float ez = ex2a(fmaf(h, G.zwh, fmaf(d2, G.zwx, G.zc)));
    float r = rcpa(1.f + er);
    float z = rcpa(1.f + ez);
    float gi2s = fmaf(d2, G.wi2n, G.bi2n);
    float gh2s = fmaf(h, G.wh2n, G.bh2n);
    float en = ex2a(fmaf(r, gh2s, gi2s));
    float n = fmaf(2.f, rcpa(1.f + en), -1.f);
    float hn = fmaf(z, h - n, n);
    if (GUARDED) h = (it >= gg) ? hn : 0.f;   // predicated select, no branch
    else         h = hn;
    float y3 = fmaf(h, G.ow, G.ob);

    float y4 = bqstep(c3, d3, s31, s32);
    float y5 = bqstep(c4, d4, s41, s42);
    float yfb = bqstep(cf, d7, sf1, sf2);
    float ov = fmaf(-fbmix, yfb, d7);

    env = fmaf(cenv, env, ccenv * fabsf(xv));
    float y0 = xv * fmaf(-depth, env, 1.f);

    d7 = d6; d6 = d5; d5 = y5; d4 = y4; d3 = y3; d2 = y2; d1 = y1; d0 = y0;
    return ov;
}

__global__ void __launch_bounds__(BLOCK, 1) amp_kernel(
    const float* __restrict__ X,     const float* __restrict__ knobs,
    const float* __restrict__ ecr,   const float* __restrict__ prep,
    const float* __restrict__ postp, const float* __restrict__ gwi,
    const float* __restrict__ gwh,   const float* __restrict__ gbi,
    const float* __restrict__ gbh,   const float* __restrict__ gow,
    const float* __restrict__ gob,   const float* __restrict__ sw1,
    const float* __restrict__ sb1,   const float* __restrict__ sw2,
    const float* __restrict__ sb2,   const float* __restrict__ fw1,
    const float* __restrict__ fb1,   const float* __restrict__ fw2,
    const float* __restrict__ fb2,   const float* __restrict__ famt,
    float* __restrict__ OUT)
{
    const int tid = blockIdx.x * BLOCK + threadIdx.x;
    if (tid >= NTHREADS) return;
    // whole warp on ONE batch row, adjacent lanes on adjacent chunks
    const int b  = tid >> 13;                 // tid / NCHUNK
    const int cp = tid & (NCHUNK - 1);

    // ---------------- per-batch setup ----------------
    const float cenv  = 1.f / (1.f + expf(-ecr[0]));
    const float ccenv = 1.f - cenv;

    const float k0 = knobs[b * 3 + 0];
    float acc = sb2[0];
#pragma unroll
    for (int j = 0; j < 8; j++) acc += sw2[j] * tanhf(fmaf(k0, sw1[j], sb1[j]));
    const float depth = 1.f / (1.f + expf(-acc));

    const Coef c1 = mk_stable(prep[0], prep[1], prep[2], prep[3], prep[4]);
    const Coef c2 = mk_stable(prep[5], prep[6], prep[7], prep[8], prep[9]);
    const Coef c3 = mk_stable(postp[0], postp[1], postp[2], postp[3], postp[4]);
    const Coef c4 = mk_stable(postp[5], postp[6], postp[7], postp[8], postp[9]);

    Coef cf;
    {
        const float k1 = knobs[b * 3 + 1], k2 = knobs[b * 3 + 2];
        float h16[16];
#pragma unroll
        for (int j = 0; j < 16; j++)
            h16[j] = tanhf(fmaf(k1, fw1[j * 2 + 0], fmaf(k2, fw1[j * 2 + 1], fb1[j])));
        float raw[5];
#pragma unroll
        for (int i = 0; i < 5; i++) {
            float a = fb2[i];
#pragma unroll
            for (int j = 0; j < 16; j++) a = fmaf(fw2[i * 16 + j], h16[j], a);
            raw[i] = a;
        }
        cf = mk_stable(raw[0], raw[1], raw[2], raw[3], raw[4]);
    }
    const float fbmix = 1.f / (1.f + expf(-famt[0]));

    const float L2E = 1.4426950408889634f;
    const float NL2E = -2.f * L2E;
    GruC G;
    G.rwx = -L2E * gwi[0]; G.rwh = -L2E * gwh[0]; G.rc = -L2E * (gbi[0] + gbh[0]);
    G.zwx = -L2E * gwi[1]; G.zwh = -L2E * gwh[1]; G.zc = -L2E * (gbi[1] + gbh[1]);
    G.wi2n = NL2E * gwi[2]; G.bi2n = NL2E * gbi[2];
    G.wh2n = NL2E * gwh[2]; G.bh2n = NL2E * gbh[2];
    G.ow = gow[0]; G.ob = gob[0];

    const float* __restrict__ xr = X + (size_t)b * L_TOTAL;
    float* __restrict__ orow     = OUT + (size_t)b * L_TOTAL;

    // ---------------- stream state ----------------
    const int fb = cp * CHUNK - FWARM;            // 16-aligned, may be negative
    int gg = 3 - fb; if (gg < 3) gg = 3;          // GRU start iter (max 67 < WSTART=72)

    float env = 0.f, h = 0.f;
    float d0 = 0.f, d1 = 0.f, d2 = 0.f, d3 = 0.f;
    float d4 = 0.f, d5 = 0.f, d6 = 0.f, d7 = 0.f;
    float s11 = 0.f, s12 = 0.f, s21 = 0.f, s22 = 0.f;
    float s31 = 0.f, s32 = 0.f, s41 = 0.f, s42 = 0.f, sf1 = 0.f, sf2 = 0.f;

    // ---------------- exact envelope pre-scan (zero-history exact) ----------------
    {
        const float cc2 = cenv * cenv, cc4 = cc2 * cc2;
        const float g0 = ccenv * cenv * cc2;
        const float g1 = ccenv * cc2;
        const float g2 = ccenv * cenv;
        const float g3 = ccenv;
        int t0 = fb - ENVW; if (t0 < 0) t0 = 0;
        float e = 0.f;
        for (int t = t0; t < fb; t += 4) {
            float4 v = *reinterpret_cast<const float4*>(xr + t);
            float a = g0 * fabsf(v.x);
            a = fmaf(g1, fabsf(v.y), a);
            a = fmaf(g2, fabsf(v.z), a);
            a = fmaf(g3, fabsf(v.w), a);
            e = fmaf(cc4, e, a);
        }
        env = e;
    }

#define PSTEP(G_, xv_, it_) pipe_step<G_>(xv_, it_, gg, c1, c2, c3, c4, cf, G, \
        cenv, ccenv, depth, fbmix, env, h, d0, d1, d2, d3, d4, d5, d6, d7,     \
        s11, s12, s21, s22, s31, s32, s41, s42, sf1, sf2)

    // ---------------- prologue (SKEW scalar iters, select-guarded) ----------------
#pragma unroll
    for (int i = 0; i < SKEW; i++) {
        int s = fb + i;
        int sa = s < 0 ? 0 : s;
        float xv = xr[sa];
        xv = (s >= 0) ? xv : 0.f;
        (void)PSTEP(true, xv, i);
    }

    // ---------------- warm loop (no stores, masked loads, guarded GRU) ----------------
    for (int i = SKEW; i < WSTART; i += 4) {
        int s = fb + i;
        int sa = s < 0 ? 0 : s;                   // 4-aligned groups: all-in or all-out
        float4 v = *reinterpret_cast<const float4*>(xr + sa);
        float m = (s >= 0) ? 1.f : 0.f;
        float xv4[4] = { v.x * m, v.y * m, v.z * m, v.w * m };
#pragma unroll
        for (int j = 0; j < 4; j++)
            (void)PSTEP(true, xv4[j], i + j);
    }

    // ---------------- output loop (unconditional stores, clean body) ----------------
    for (int i = WSTART; i < ITERS; i += 4) {
        int s = fb + i;
        int sa = s > (L_TOTAL - 4) ? (L_TOTAL - 4) : s;  // tail over-read is dead data
        float4 v = *reinterpret_cast<const float4*>(xr + sa);
        float xv4[4] = { v.x, v.y, v.z, v.w };
        float ov4[4];
#pragma unroll
        for (int j = 0; j < 4; j++)
            ov4[j] = PSTEP(false, xv4[j], i + j);
        float4 o; o.x = ov4[0]; o.y = ov4[1]; o.z = ov4[2]; o.w = ov4[3];
        *reinterpret_cast<float4*>(orow + (s - SKEW)) = o;
    }
#undef PSTEP
}

extern "C" void kernel_launch(void* const* d_in, const int* in_sizes, int n_in,
                              void* d_out, int out_size)
{
    const float* X     = (const float*)d_in[0];
    const float* knobs = (const float*)d_in[1];
    const float* ecr   = (const float*)d_in[2];
    const float* prep  = (const float*)d_in[3];
    const float* postp = (const float*)d_in[4];
    const float* gwi   = (const float*)d_in[5];
    const float* gwh   = (const float*)d_in[6];
    const float* gbi   = (const float*)d_in[7];
    const float* gbh   = (const float*)d_in[8];
    const float* gow   = (const float*)d_in[9];
    const float* gob   = (const float*)d_in[10];
    const float* sw1   = (const float*)d_in[11];
    const float* sb1   = (const float*)d_in[12];
    const float* sw2   = (const float*)d_in[13];
    const float* sb2   = (const float*)d_in[14];
    const float* fw1   = (const float*)d_in[15];
    const float* fb1   = (const float*)d_in[16];
    const float* fw2   = (const float*)d_in[17];
    const float* fb2   = (const float*)d_in[18];
    const float* famt  = (const float*)d_in[19];
    float* OUT = (float*)d_out;

    dim3 grid(NTHREADS / BLOCK);   // 128 blocks x 512 threads: 4 warps per SMSP
    amp_kernel<<<grid, BLOCK>>>(X, knobs, ecr, prep, postp, gwi, gwh, gbi, gbh,
                                gow, gob, sw1, sb1, sw2, sb2, fw1, fb1, fw2, fb2,
                                famt, OUT);
}